// round 6
// baseline (speedup 1.0000x reference)
#include <cuda_runtime.h>

// SSIM loss — vertical-first fused kernel, fully f32x2 (sm_103a FFMA2).
// Stage V: per-thread column vertical 11-tap conv of (a,b) and (p,q)=(a²+b²,ab)
//          field-packed in f32x2 registers, straight from gmem.
//          Store transposed into row-pair planar smem: (A0,A1,B0,B1) per elem.
// Stage H: horizontal 11-tap conv AND SSIM epilogue entirely in f32x2 over
//          row-pairs (2 vertically adjacent pixels per op). Clamp on ALU pipe.
// Single kernel: last-block-done reduction writes out[0] and resets state.

#define NT      256
#define EXTX    64
#define TILE_X  54
#define TILE_Y  48
#define R       12
#define NRP     24          // row pairs per tile
#define SHS     67          // smem stride in 16B elems (cols 0..65 used, odd)
#define IMG     512
#define GRIDX   10
#define GRIDY   11
#define NBLK    (GRIDX * GRIDY * 48)

#define KWc0 0.0010283801f
#define KWc1 0.0075987582f
#define KWc2 0.0360007696f
#define KWc3 0.1093606947f
#define KWc4 0.2130055430f
#define KWc5 0.2660117300f

#define C1V 0.0001f
#define C2V 0.0009f

__device__ float    g_sum = 0.0f;
__device__ unsigned g_cnt = 0u;

__device__ __forceinline__ void fma2(float2& d, float2 a, float2 b) {
    asm("fma.rn.f32x2 %0, %1, %2, %0;"
        : "+l"(reinterpret_cast<unsigned long long&>(d))
        : "l"(reinterpret_cast<const unsigned long long&>(a)),
          "l"(reinterpret_cast<const unsigned long long&>(b)));
}
__device__ __forceinline__ float2 fma2o(float2 a, float2 b, float2 c) {
    float2 d;
    asm("fma.rn.f32x2 %0, %1, %2, %3;"
        : "=l"(reinterpret_cast<unsigned long long&>(d))
        : "l"(reinterpret_cast<const unsigned long long&>(a)),
          "l"(reinterpret_cast<const unsigned long long&>(b)),
          "l"(reinterpret_cast<const unsigned long long&>(c)));
    return d;
}
__device__ __forceinline__ float2 mul2(float2 a, float2 b) {
    float2 d;
    asm("mul.rn.f32x2 %0, %1, %2;"
        : "=l"(reinterpret_cast<unsigned long long&>(d))
        : "l"(reinterpret_cast<const unsigned long long&>(a)),
          "l"(reinterpret_cast<const unsigned long long&>(b)));
    return d;
}
__device__ __forceinline__ float2 add2(float2 a, float2 b) {
    float2 d;
    asm("add.rn.f32x2 %0, %1, %2;"
        : "=l"(reinterpret_cast<unsigned long long&>(d))
        : "l"(reinterpret_cast<const unsigned long long&>(a)),
          "l"(reinterpret_cast<const unsigned long long&>(b)));
    return d;
}

__global__ void __launch_bounds__(NT, 3)
ssim_rp_kernel(const float* __restrict__ img1,
               const float* __restrict__ img2,
               float* __restrict__ out)
{
    float2 wpair[6];
    wpair[0] = make_float2(KWc0, KWc0); wpair[1] = make_float2(KWc1, KWc1);
    wpair[2] = make_float2(KWc2, KWc2); wpair[3] = make_float2(KWc3, KWc3);
    wpair[4] = make_float2(KWc4, KWc4); wpair[5] = make_float2(KWc5, KWc5);
    #define WPK(k) wpair[(k) <= 5 ? (k) : 10 - (k)]

    extern __shared__ float4 smem[];
    float4* sAB = smem;                // [NRP][SHS] : (A0,A1,B0,B1)
    float4* sPQ = smem + NRP * SHS;    // [NRP][SHS] : (P0,P1,Q0,Q1)

    const int tid  = threadIdx.x;
    const int base = blockIdx.z * (IMG * IMG);
    const int x0   = blockIdx.x * TILE_X;
    const int y0   = blockIdx.y * TILE_Y;

    const bool interior = (x0 >= 5) && (x0 + EXTX - 5 <= IMG) &&
                          (y0 >= 5) && (y0 + TILE_Y + 5 <= IMG);

    // zero-fill halo columns 64,65 of both planes (read by last chunk's window)
    if (tid < NRP * 2) {
        int rp = tid >> 1, cc = 64 + (tid & 1);
        sAB[rp * SHS + cc] = make_float4(0.f, 0.f, 0.f, 0.f);
        sPQ[rp * SHS + cc] = make_float4(0.f, 0.f, 0.f, 0.f);
    }

    // ---------------- Stage V: vertical 11-tap, f32x2 registers ------------
    {
        const int c   = tid & (EXTX - 1);
        const int g   = tid >> 6;            // row group 0..3 (R rows each)
        const int gx  = x0 - 5 + c;
        const int iy0 = y0 + g * R - 5;

        float2 accAB[R], accPQ[R];
        #pragma unroll
        for (int o = 0; o < R; ++o) {
            accAB[o] = make_float2(0.f, 0.f);
            accPQ[o] = make_float2(0.f, 0.f);
        }

        if (interior) {
            const float* p1 = img1 + base + iy0 * IMG + gx;
            const float* p2 = img2 + base + iy0 * IMG + gx;
            #pragma unroll
            for (int j = 0; j < R + 10; ++j) {
                float a = __ldg(p1 + j * IMG);
                float b = __ldg(p2 + j * IMG);
                float2 ab = make_float2(a, b);
                float2 pq = make_float2(a * a + b * b, a * b);
                #pragma unroll
                for (int o = 0; o < R; ++o) {
                    int k = j - o;
                    if (k >= 0 && k <= 10) {
                        fma2(accAB[o], WPK(k), ab);
                        fma2(accPQ[o], WPK(k), pq);
                    }
                }
            }
        } else {
            const bool xok = (unsigned)gx < (unsigned)IMG;
            #pragma unroll
            for (int j = 0; j < R + 10; ++j) {
                int gy = iy0 + j;
                float a = 0.f, b = 0.f;
                if (xok && (unsigned)gy < (unsigned)IMG) {
                    int off = base + gy * IMG + gx;
                    a = __ldg(img1 + off);
                    b = __ldg(img2 + off);
                }
                float2 ab = make_float2(a, b);
                float2 pq = make_float2(a * a + b * b, a * b);
                #pragma unroll
                for (int o = 0; o < R; ++o) {
                    int k = j - o;
                    if (k >= 0 && k <= 10) {
                        fma2(accAB[o], WPK(k), ab);
                        fma2(accPQ[o], WPK(k), pq);
                    }
                }
            }
        }

        // transpose field-packed -> row-pair planar and store
        #pragma unroll
        for (int r = 0; r < R / 2; ++r) {
            int rp = g * (R / 2) + r;
            float2 e0 = accAB[2 * r], e1 = accAB[2 * r + 1];
            sAB[rp * SHS + c] = make_float4(e0.x, e1.x, e0.y, e1.y);
            float2 f0 = accPQ[2 * r], f1 = accPQ[2 * r + 1];
            sPQ[rp * SHS + c] = make_float4(f0.x, f1.x, f0.y, f1.y);
        }
    }
    __syncthreads();

    // ------- Stage H: horizontal 11-tap + SSIM, f32x2 row-pairs ------------
    const float2 TWO2  = make_float2( 2.0f,  2.0f);
    const float2 NTWO2 = make_float2(-2.0f, -2.0f);
    const float2 NONE2 = make_float2(-1.0f, -1.0f);
    const float2 C1P   = make_float2(C1V, C1V);
    const float2 C2P   = make_float2(C2V, C2V);
    const float2 CCP   = make_float2(C1V + C2V, C1V + C2V);
    const float2 ZERO2 = make_float2(0.f, 0.f);

    float2 loss2 = make_float2(0.f, 0.f);

    for (int t = tid; t < NRP * 14; t += NT) {     // 24 rps x 14 chunks = 336
        int rp = t % NRP;
        int c0 = (t / NRP) * 4;

        int gy0 = y0 + 2 * rp;
        float2 rowm = make_float2(gy0 < IMG ? 1.f : 0.f,
                                  gy0 + 1 < IMG ? 1.f : 0.f);

        float2 aA[4], aB[4], aP[4], aQ[4];
        #pragma unroll
        for (int cc = 0; cc < 4; ++cc) {
            aA[cc] = ZERO2; aB[cc] = ZERO2; aP[cc] = ZERO2; aQ[cc] = ZERO2;
        }

        #pragma unroll
        for (int i = 0; i < 14; ++i) {
            float4 vab = sAB[rp * SHS + c0 + i];
            float4 vpq = sPQ[rp * SHS + c0 + i];
            float2 A2 = make_float2(vab.x, vab.y);
            float2 B2 = make_float2(vab.z, vab.w);
            float2 P2 = make_float2(vpq.x, vpq.y);
            float2 Q2 = make_float2(vpq.z, vpq.w);
            #pragma unroll
            for (int cc = 0; cc < 4; ++cc) {
                int k = i - cc;
                if (k >= 0 && k <= 10) {
                    fma2(aA[cc], WPK(k), A2);
                    fma2(aB[cc], WPK(k), B2);
                    fma2(aP[cc], WPK(k), P2);
                    fma2(aQ[cc], WPK(k), Q2);
                }
            }
        }

        #pragma unroll
        for (int cc = 0; cc < 4; ++cc) {
            int col = c0 + cc;
            bool valid = (col < TILE_X) && (x0 + col < IMG);
            float2 m = valid ? rowm : ZERO2;

            float2 A2 = aA[cc], B2 = aB[cc], P2 = aP[cc], Q2 = aQ[cc];
            float2 AB   = mul2(A2, B2);
            float2 num1 = fma2o(AB, TWO2, C1P);        // 2AB + C1
            float2 tq   = fma2o(Q2, TWO2, C2P);        // 2Q  + C2
            float2 num2 = fma2o(AB, NTWO2, tq);        // 2(Q-AB) + C2
            float2 den1 = fma2o(B2, B2, C1P);
            den1        = fma2o(A2, A2, den1);         // A²+B²+C1
            float2 den2 = fma2o(den1, NONE2, P2);      // P - den1
            den2        = add2(den2, CCP);             // P-A²-B²+C2
            float2 num  = mul2(num1, num2);
            float2 den  = mul2(den1, den2);

            float2 l;
            l.x = fmaf(__fdividef(num.x, den.x), -0.5f, 0.5f);
            l.y = fmaf(__fdividef(num.y, den.y), -0.5f, 0.5f);
            l.x = fminf(fmaxf(l.x, 0.f), 0.5f);        // kills NaN/Inf too
            l.y = fminf(fmaxf(l.y, 0.f), 0.5f);
            fma2(loss2, l, m);                         // loss2 += l * mask
        }
    }

    // ---------------- Block reduction + last-block finish -------------------
    float loss = loss2.x + loss2.y;
    #pragma unroll
    for (int s = 16; s > 0; s >>= 1)
        loss += __shfl_xor_sync(0xFFFFFFFFu, loss, s);

    __shared__ float warpsum[NT / 32];
    if ((tid & 31) == 0) warpsum[tid >> 5] = loss;
    __syncthreads();
    if (tid == 0) {
        float bsum = 0.f;
        #pragma unroll
        for (int w = 0; w < NT / 32; ++w) bsum += warpsum[w];
        atomicAdd(&g_sum, bsum);
        __threadfence();
        unsigned ticket = atomicAdd(&g_cnt, 1u);
        if (ticket == NBLK - 1) {
            float total = atomicAdd(&g_sum, 0.0f);     // coherent read
            const float inv_total = 1.0f / (16.0f * 3.0f * 512.0f * 512.0f);
            out[0] = total * inv_total;
            g_sum = 0.0f;                              // reset for next replay
            g_cnt = 0u;
        }
    }
}

extern "C" void kernel_launch(void* const* d_in, const int* in_sizes, int n_in,
                              void* d_out, int out_size)
{
    const float* img1 = (const float*)d_in[0];
    const float* img2 = (const float*)d_in[1];
    float* out = (float*)d_out;

    const int smem_bytes = 2 * NRP * SHS * (int)sizeof(float4);  // 51456
    cudaFuncSetAttribute(ssim_rp_kernel,
                         cudaFuncAttributeMaxDynamicSharedMemorySize, smem_bytes);

    dim3 grid(GRIDX, GRIDY, 48);   // 10 x 11 x 48 = 5280 blocks
    ssim_rp_kernel<<<grid, NT, smem_bytes>>>(img1, img2, out);
}

// round 7
// speedup vs baseline: 1.0097x; 1.0097x over previous
#include <cuda_runtime.h>

// SSIM loss — vertical-first fused kernel (R5 structure) with:
//  - f32x2 conv (fields packed as (a,b) and (p,q)=(a²+b²,ab))
//  - f32x2 epilogue packed across column pairs (in-place register repack)
//  - single kernel: last-block-done reduction (no zeroing kernel)

#define NT      256
#define EXTX    64
#define TILE_X  54
#define TILE_Y  48
#define R       12
#define SVS     65          // row stride in 16B elements (odd -> conflict-free)
#define IMG     512
#define GRIDX   10
#define GRIDY   11
#define NBLK    (GRIDX * GRIDY * 48)

#define KWc0 0.0010283801f
#define KWc1 0.0075987582f
#define KWc2 0.0360007696f
#define KWc3 0.1093606947f
#define KWc4 0.2130055430f
#define KWc5 0.2660117300f

#define C1V 0.0001f
#define C2V 0.0009f

__device__ float    g_sum = 0.0f;
__device__ unsigned g_cnt = 0u;

__device__ __forceinline__ void fma2(float2& d, float2 a, float2 b) {
    asm("fma.rn.f32x2 %0, %1, %2, %0;"
        : "+l"(reinterpret_cast<unsigned long long&>(d))
        : "l"(reinterpret_cast<const unsigned long long&>(a)),
          "l"(reinterpret_cast<const unsigned long long&>(b)));
}
__device__ __forceinline__ float2 fma2o(float2 a, float2 b, float2 c) {
    float2 d;
    asm("fma.rn.f32x2 %0, %1, %2, %3;"
        : "=l"(reinterpret_cast<unsigned long long&>(d))
        : "l"(reinterpret_cast<const unsigned long long&>(a)),
          "l"(reinterpret_cast<const unsigned long long&>(b)),
          "l"(reinterpret_cast<const unsigned long long&>(c)));
    return d;
}
__device__ __forceinline__ float2 mul2(float2 a, float2 b) {
    float2 d;
    asm("mul.rn.f32x2 %0, %1, %2;"
        : "=l"(reinterpret_cast<unsigned long long&>(d))
        : "l"(reinterpret_cast<const unsigned long long&>(a)),
          "l"(reinterpret_cast<const unsigned long long&>(b)));
    return d;
}
__device__ __forceinline__ float2 add2(float2 a, float2 b) {
    float2 d;
    asm("add.rn.f32x2 %0, %1, %2;"
        : "=l"(reinterpret_cast<unsigned long long&>(d))
        : "l"(reinterpret_cast<const unsigned long long&>(a)),
          "l"(reinterpret_cast<const unsigned long long&>(b)));
    return d;
}

__global__ void __launch_bounds__(NT, 3)
ssim_f32x2_kernel(const float* __restrict__ img1,
                  const float* __restrict__ img2,
                  float* __restrict__ out)
{
    float2 wpair[6];
    wpair[0] = make_float2(KWc0, KWc0); wpair[1] = make_float2(KWc1, KWc1);
    wpair[2] = make_float2(KWc2, KWc2); wpair[3] = make_float2(KWc3, KWc3);
    wpair[4] = make_float2(KWc4, KWc4); wpair[5] = make_float2(KWc5, KWc5);
    #define WPK(k) wpair[(k) <= 5 ? (k) : 10 - (k)]

    extern __shared__ float4 sV[];   // [TILE_Y][SVS] : (A,B,P,Q) vertical-filtered

    const int tid  = threadIdx.x;
    const int base = blockIdx.z * (IMG * IMG);
    const int x0   = blockIdx.x * TILE_X;
    const int y0   = blockIdx.y * TILE_Y;

    const bool interior = (x0 >= 5) && (x0 + EXTX - 5 <= IMG) &&
                          (y0 >= 5) && (y0 + TILE_Y + 5 <= IMG);

    // ---------------- Stage V: vertical 11-tap, f32x2 registers ------------
    {
        const int c   = tid & (EXTX - 1);
        const int g   = tid >> 6;            // row group 0..3
        const int gx  = x0 - 5 + c;
        const int iy0 = y0 + g * R - 5;

        float2 accAB[R], accPQ[R];
        #pragma unroll
        for (int o = 0; o < R; ++o) {
            accAB[o] = make_float2(0.f, 0.f);
            accPQ[o] = make_float2(0.f, 0.f);
        }

        if (interior) {
            const float* p1 = img1 + base + iy0 * IMG + gx;
            const float* p2 = img2 + base + iy0 * IMG + gx;
            #pragma unroll
            for (int j = 0; j < R + 10; ++j) {
                float a = __ldg(p1 + j * IMG);
                float b = __ldg(p2 + j * IMG);
                float2 ab = make_float2(a, b);
                float2 pq = make_float2(a * a + b * b, a * b);
                #pragma unroll
                for (int o = 0; o < R; ++o) {
                    int k = j - o;
                    if (k >= 0 && k <= 10) {
                        fma2(accAB[o], WPK(k), ab);
                        fma2(accPQ[o], WPK(k), pq);
                    }
                }
            }
        } else {
            const bool xok = (unsigned)gx < (unsigned)IMG;
            #pragma unroll
            for (int j = 0; j < R + 10; ++j) {
                int gy = iy0 + j;
                float a = 0.f, b = 0.f;
                if (xok && (unsigned)gy < (unsigned)IMG) {
                    int off = base + gy * IMG + gx;
                    a = __ldg(img1 + off);
                    b = __ldg(img2 + off);
                }
                float2 ab = make_float2(a, b);
                float2 pq = make_float2(a * a + b * b, a * b);
                #pragma unroll
                for (int o = 0; o < R; ++o) {
                    int k = j - o;
                    if (k >= 0 && k <= 10) {
                        fma2(accAB[o], WPK(k), ab);
                        fma2(accPQ[o], WPK(k), pq);
                    }
                }
            }
        }

        #pragma unroll
        for (int o = 0; o < R; ++o)
            sV[(g * R + o) * SVS + c] =
                make_float4(accAB[o].x, accAB[o].y, accPQ[o].x, accPQ[o].y);
    }
    __syncthreads();

    // ------- Stage H: j-streaming horizontal 11-tap + packed SSIM ----------
    const float2 TWO2  = make_float2( 2.0f,  2.0f);
    const float2 NTWO2 = make_float2(-2.0f, -2.0f);
    const float2 NONE2 = make_float2(-1.0f, -1.0f);
    const float2 C1P   = make_float2(C1V, C1V);
    const float2 C2P   = make_float2(C2V, C2V);
    const float2 CCP   = make_float2(C1V + C2V, C1V + C2V);
    const float2 ZERO2 = make_float2(0.f, 0.f);

    float2 loss2 = make_float2(0.f, 0.f);

    for (int t = tid; t < 9 * TILE_Y; t += NT) {     // 9 chunks x 48 rows
        int row = t % TILE_Y;
        int c0  = (t / TILE_Y) * 6;

        float2 oAB[6], oPQ[6];
        #pragma unroll
        for (int cc = 0; cc < 6; ++cc) { oAB[cc] = ZERO2; oPQ[cc] = ZERO2; }

        #pragma unroll
        for (int j = 0; j < 16; ++j) {
            float4 v = sV[row * SVS + c0 + j];
            float2 vab = make_float2(v.x, v.y);
            float2 vpq = make_float2(v.z, v.w);
            #pragma unroll
            for (int cc = 0; cc < 6; ++cc) {
                int k = j - cc;
                if (k >= 0 && k <= 10) {
                    fma2(oAB[cc], WPK(k), vab);
                    fma2(oPQ[cc], WPK(k), vpq);
                }
            }
        }

        int  gy  = y0 + row;
        int  ox0 = x0 + c0;
        float yokf = (gy < IMG) ? 1.0f : 0.0f;

        // epilogue packed across column pairs (cc, cc+1)
        #pragma unroll
        for (int cp = 0; cp < 3; ++cp) {
            int cc = 2 * cp;
            float2 A2 = make_float2(oAB[cc].x, oAB[cc + 1].x);
            float2 B2 = make_float2(oAB[cc].y, oAB[cc + 1].y);
            float2 P2 = make_float2(oPQ[cc].x, oPQ[cc + 1].x);
            float2 Q2 = make_float2(oPQ[cc].y, oPQ[cc + 1].y);

            float2 AB   = mul2(A2, B2);
            float2 num1 = fma2o(AB, TWO2, C1P);          // 2AB + C1
            float2 tq   = fma2o(Q2, TWO2, C2P);          // 2Q  + C2
            float2 num2 = fma2o(AB, NTWO2, tq);          // 2(Q-AB) + C2
            float2 den1 = fma2o(B2, B2, C1P);
            den1        = fma2o(A2, A2, den1);           // A²+B²+C1
            float2 den2 = fma2o(den1, NONE2, P2);        // P - den1
            den2        = add2(den2, CCP);               // P-A²-B²+C2
            float2 num  = mul2(num1, num2);
            float2 den  = mul2(den1, den2);

            float2 l;
            l.x = fmaf(__fdividef(num.x, den.x), -0.5f, 0.5f);
            l.y = fmaf(__fdividef(num.y, den.y), -0.5f, 0.5f);
            l.x = fminf(fmaxf(l.x, 0.f), 0.5f);          // clip (NaN-safe)
            l.y = fminf(fmaxf(l.y, 0.f), 0.5f);

            float2 m;
            m.x = (ox0 + cc     < IMG) ? yokf : 0.0f;
            m.y = (ox0 + cc + 1 < IMG) ? yokf : 0.0f;
            fma2(loss2, l, m);                           // loss2 += l * mask
        }
    }

    // ---------------- Block reduction + last-block finish -------------------
    float loss = loss2.x + loss2.y;
    #pragma unroll
    for (int s = 16; s > 0; s >>= 1)
        loss += __shfl_xor_sync(0xFFFFFFFFu, loss, s);

    __shared__ float warpsum[NT / 32];
    if ((tid & 31) == 0) warpsum[tid >> 5] = loss;
    __syncthreads();
    if (tid == 0) {
        float bsum = 0.f;
        #pragma unroll
        for (int w = 0; w < NT / 32; ++w) bsum += warpsum[w];
        atomicAdd(&g_sum, bsum);
        __threadfence();
        unsigned ticket = atomicAdd(&g_cnt, 1u);
        if (ticket == NBLK - 1) {
            float total = atomicAdd(&g_sum, 0.0f);       // coherent read
            const float inv_total = 1.0f / (16.0f * 3.0f * 512.0f * 512.0f);
            out[0] = total * inv_total;
            g_sum = 0.0f;                                // reset for next replay
            g_cnt = 0u;
        }
    }
}

extern "C" void kernel_launch(void* const* d_in, const int* in_sizes, int n_in,
                              void* d_out, int out_size)
{
    const float* img1 = (const float*)d_in[0];
    const float* img2 = (const float*)d_in[1];
    float* out = (float*)d_out;

    const int smem_bytes = TILE_Y * SVS * (int)sizeof(float4);  // 49920
    cudaFuncSetAttribute(ssim_f32x2_kernel,
                         cudaFuncAttributeMaxDynamicSharedMemorySize, smem_bytes);

    dim3 grid(GRIDX, GRIDY, 48);   // 10 x 11 x 48 = 5280 blocks
    ssim_f32x2_kernel<<<grid, NT, smem_bytes>>>(img1, img2, out);
}

// round 8
// speedup vs baseline: 1.0647x; 1.0545x over previous
#include <cuda_runtime.h>

// SSIM loss — vertical-first fused kernel (R5 conv structure) with:
//  - f32x2 conv (fields packed as (a,b) and (p,q)=(a²+b²,ab))
//  - TILE_Y=32 (exact y tiling, 16x32=512), R=8 -> 32 acc regs -> 4 CTAs/SM
//  - Stage H: 8 chunks x 7 outputs x 32 rows = 256 tasks (perfect balance)
//  - single kernel: last-block-done reduction (no zeroing kernel)

#define NT      256
#define EXTX    64
#define TILE_X  54
#define TILE_Y  32
#define R       8
#define SVS     65          // row stride in 16B elements (odd -> conflict-free)
#define IMG     512
#define GRIDX   10
#define GRIDY   16
#define NBLK    (GRIDX * GRIDY * 48)

#define KWc0 0.0010283801f
#define KWc1 0.0075987582f
#define KWc2 0.0360007696f
#define KWc3 0.1093606947f
#define KWc4 0.2130055430f
#define KWc5 0.2660117300f

#define C1V 0.0001f
#define C2V 0.0009f

__device__ float    g_sum = 0.0f;
__device__ unsigned g_cnt = 0u;

__device__ __forceinline__ void fma2(float2& d, float2 a, float2 b) {
    asm("fma.rn.f32x2 %0, %1, %2, %0;"
        : "+l"(reinterpret_cast<unsigned long long&>(d))
        : "l"(reinterpret_cast<const unsigned long long&>(a)),
          "l"(reinterpret_cast<const unsigned long long&>(b)));
}

__global__ void __launch_bounds__(NT, 4)
ssim_t32_kernel(const float* __restrict__ img1,
                const float* __restrict__ img2,
                float* __restrict__ out)
{
    float2 wpair[6];
    wpair[0] = make_float2(KWc0, KWc0); wpair[1] = make_float2(KWc1, KWc1);
    wpair[2] = make_float2(KWc2, KWc2); wpair[3] = make_float2(KWc3, KWc3);
    wpair[4] = make_float2(KWc4, KWc4); wpair[5] = make_float2(KWc5, KWc5);
    #define WPK(k) wpair[(k) <= 5 ? (k) : 10 - (k)]

    extern __shared__ float4 sV[];   // [TILE_Y][SVS]+pad : (A,B,P,Q)

    const int tid  = threadIdx.x;
    const int base = blockIdx.z * (IMG * IMG);
    const int x0   = blockIdx.x * TILE_X;
    const int y0   = blockIdx.y * TILE_Y;

    const bool interior = (x0 >= 5) && (x0 + EXTX - 5 <= IMG) &&
                          (y0 >= 5) && (y0 + TILE_Y + 5 <= IMG);

    // ---------------- Stage V: vertical 11-tap, f32x2 registers ------------
    {
        const int c   = tid & (EXTX - 1);
        const int g   = tid >> 6;            // row group 0..3 (R rows each)
        const int gx  = x0 - 5 + c;
        const int iy0 = y0 + g * R - 5;

        float2 accAB[R], accPQ[R];
        #pragma unroll
        for (int o = 0; o < R; ++o) {
            accAB[o] = make_float2(0.f, 0.f);
            accPQ[o] = make_float2(0.f, 0.f);
        }

        if (interior) {
            const float* p1 = img1 + base + iy0 * IMG + gx;
            const float* p2 = img2 + base + iy0 * IMG + gx;
            #pragma unroll
            for (int j = 0; j < R + 10; ++j) {
                float a = __ldg(p1 + j * IMG);
                float b = __ldg(p2 + j * IMG);
                float2 ab = make_float2(a, b);
                float2 pq = make_float2(a * a + b * b, a * b);
                #pragma unroll
                for (int o = 0; o < R; ++o) {
                    int k = j - o;
                    if (k >= 0 && k <= 10) {
                        fma2(accAB[o], WPK(k), ab);
                        fma2(accPQ[o], WPK(k), pq);
                    }
                }
            }
        } else {
            const bool xok = (unsigned)gx < (unsigned)IMG;
            #pragma unroll
            for (int j = 0; j < R + 10; ++j) {
                int gy = iy0 + j;
                float a = 0.f, b = 0.f;
                if (xok && (unsigned)gy < (unsigned)IMG) {
                    int off = base + gy * IMG + gx;
                    a = __ldg(img1 + off);
                    b = __ldg(img2 + off);
                }
                float2 ab = make_float2(a, b);
                float2 pq = make_float2(a * a + b * b, a * b);
                #pragma unroll
                for (int o = 0; o < R; ++o) {
                    int k = j - o;
                    if (k >= 0 && k <= 10) {
                        fma2(accAB[o], WPK(k), ab);
                        fma2(accPQ[o], WPK(k), pq);
                    }
                }
            }
        }

        #pragma unroll
        for (int o = 0; o < R; ++o)
            sV[(g * R + o) * SVS + c] =
                make_float4(accAB[o].x, accAB[o].y, accPQ[o].x, accPQ[o].y);
    }
    __syncthreads();

    // ------- Stage H: 11-tap + SSIM; 8 chunks x 7 outputs, 256 tasks -------
    float loss = 0.0f;
    {
        const int row = tid & (TILE_Y - 1);      // 0..31
        const int c0  = (tid >> 5) * 7;          // 0,7,...,49

        float2 oAB[7], oPQ[7];
        #pragma unroll
        for (int cc = 0; cc < 7; ++cc) {
            oAB[cc] = make_float2(0.f, 0.f);
            oPQ[cc] = make_float2(0.f, 0.f);
        }

        #pragma unroll
        for (int j = 0; j < 17; ++j) {
            float4 v = sV[row * SVS + c0 + j];   // cols 54..55 read pad/garbage
            float2 vab = make_float2(v.x, v.y);  // (masked outputs only)
            float2 vpq = make_float2(v.z, v.w);
            #pragma unroll
            for (int cc = 0; cc < 7; ++cc) {
                int k = j - cc;
                if (k >= 0 && k <= 10) {
                    fma2(oAB[cc], WPK(k), vab);
                    fma2(oPQ[cc], WPK(k), vpq);
                }
            }
        }

        const int ox0 = x0 + c0;
        #pragma unroll
        for (int cc = 0; cc < 7; ++cc) {
            float A = oAB[cc].x, B = oAB[cc].y;
            float P = oPQ[cc].x, Q = oPQ[cc].y;
            float AB   = A * B;
            float AA   = A * A;
            float num1 = 2.0f * AB + C1V;
            float num2 = 2.0f * (Q - AB) + C2V;
            float den1 = fmaf(B, B, C1V) + AA;           // AA+BB+C1
            float den2 = (P - den1) + (C1V + C2V);       // P-AA-BB+C2
            float ssim = __fdividef(num1 * num2, den1 * den2);
            float l    = fmaf(ssim, -0.5f, 0.5f);        // (1-ssim)/2
            l = fminf(fmaxf(l, 0.0f), 0.5f);             // clip (NaN-safe)
            if ((c0 + cc) < TILE_X && (ox0 + cc) < IMG) loss += l;
        }
    }

    // ---------------- Block reduction + last-block finish -------------------
    #pragma unroll
    for (int s = 16; s > 0; s >>= 1)
        loss += __shfl_xor_sync(0xFFFFFFFFu, loss, s);

    __shared__ float warpsum[NT / 32];
    if ((tid & 31) == 0) warpsum[tid >> 5] = loss;
    __syncthreads();
    if (tid == 0) {
        float bsum = 0.f;
        #pragma unroll
        for (int w = 0; w < NT / 32; ++w) bsum += warpsum[w];
        atomicAdd(&g_sum, bsum);
        __threadfence();
        unsigned ticket = atomicAdd(&g_cnt, 1u);
        if (ticket == NBLK - 1) {
            float total = atomicAdd(&g_sum, 0.0f);       // coherent read
            const float inv_total = 1.0f / (16.0f * 3.0f * 512.0f * 512.0f);
            out[0] = total * inv_total;
            g_sum = 0.0f;                                // reset for next replay
            g_cnt = 0u;
        }
    }
}

extern "C" void kernel_launch(void* const* d_in, const int* in_sizes, int n_in,
                              void* d_out, int out_size)
{
    const float* img1 = (const float*)d_in[0];
    const float* img2 = (const float*)d_in[1];
    float* out = (float*)d_out;

    // +2 pad elements: widest H window (row 31, col 65) stays in bounds
    const int smem_bytes = (TILE_Y * SVS + 2) * (int)sizeof(float4);  // 33312
    cudaFuncSetAttribute(ssim_t32_kernel,
                         cudaFuncAttributeMaxDynamicSharedMemorySize, smem_bytes);

    dim3 grid(GRIDX, GRIDY, 48);   // 10 x 16 x 48 = 7680 blocks
    ssim_t32_kernel<<<grid, NT, smem_bytes>>>(img1, img2, out);
}

// round 9
// speedup vs baseline: 1.0702x; 1.0052x over previous
#include <cuda_runtime.h>

// SSIM loss — vertical-first fused kernel (R5 structure, tuned):
//  - f32x2 conv (fields packed as (a,b) and (p,q)=(a²+b²,ab))
//  - TILE_Y=52 (R=13): y-waste 1.6%, V-halo redundancy 1.77x,
//    stage-H 468 tasks -> 91.4% round utilization, zero x-chunk mask waste
//  - scalar SSIM epilogue (R5-proven)
//  - single kernel: last-block-done reduction (no zeroing kernel)

#define NT      256
#define EXTX    64
#define TILE_X  54
#define TILE_Y  52
#define R       13
#define SVS     65          // row stride in 16B elements (odd -> conflict-free)
#define IMG     512
#define GRIDX   10
#define GRIDY   10
#define NBLK    (GRIDX * GRIDY * 48)

#define KWc0 0.0010283801f
#define KWc1 0.0075987582f
#define KWc2 0.0360007696f
#define KWc3 0.1093606947f
#define KWc4 0.2130055430f
#define KWc5 0.2660117300f

#define C1V 0.0001f
#define C2V 0.0009f

__device__ float    g_sum = 0.0f;
__device__ unsigned g_cnt = 0u;

__device__ __forceinline__ void fma2(float2& d, float2 a, float2 b) {
    asm("fma.rn.f32x2 %0, %1, %2, %0;"
        : "+l"(reinterpret_cast<unsigned long long&>(d))
        : "l"(reinterpret_cast<const unsigned long long&>(a)),
          "l"(reinterpret_cast<const unsigned long long&>(b)));
}

__global__ void __launch_bounds__(NT, 3)
ssim_t52_kernel(const float* __restrict__ img1,
                const float* __restrict__ img2,
                float* __restrict__ out)
{
    float2 wpair[6];
    wpair[0] = make_float2(KWc0, KWc0); wpair[1] = make_float2(KWc1, KWc1);
    wpair[2] = make_float2(KWc2, KWc2); wpair[3] = make_float2(KWc3, KWc3);
    wpair[4] = make_float2(KWc4, KWc4); wpair[5] = make_float2(KWc5, KWc5);
    #define WPK(k) wpair[(k) <= 5 ? (k) : 10 - (k)]

    extern __shared__ float4 sV[];   // [TILE_Y][SVS] : (A,B,P,Q) vertical-filtered

    const int tid  = threadIdx.x;
    const int base = blockIdx.z * (IMG * IMG);
    const int x0   = blockIdx.x * TILE_X;
    const int y0   = blockIdx.y * TILE_Y;

    const bool interior = (x0 >= 5) && (x0 + EXTX - 5 <= IMG) &&
                          (y0 >= 5) && (y0 + TILE_Y + 5 <= IMG);

    // ---------------- Stage V: vertical 11-tap, f32x2 registers ------------
    {
        const int c   = tid & (EXTX - 1);
        const int g   = tid >> 6;            // row group 0..3 (R rows each)
        const int gx  = x0 - 5 + c;
        const int iy0 = y0 + g * R - 5;

        float2 accAB[R], accPQ[R];
        #pragma unroll
        for (int o = 0; o < R; ++o) {
            accAB[o] = make_float2(0.f, 0.f);
            accPQ[o] = make_float2(0.f, 0.f);
        }

        if (interior) {
            const float* p1 = img1 + base + iy0 * IMG + gx;
            const float* p2 = img2 + base + iy0 * IMG + gx;
            #pragma unroll
            for (int j = 0; j < R + 10; ++j) {
                float a = __ldg(p1 + j * IMG);
                float b = __ldg(p2 + j * IMG);
                float2 ab = make_float2(a, b);
                float2 pq = make_float2(a * a + b * b, a * b);
                #pragma unroll
                for (int o = 0; o < R; ++o) {
                    int k = j - o;
                    if (k >= 0 && k <= 10) {
                        fma2(accAB[o], WPK(k), ab);
                        fma2(accPQ[o], WPK(k), pq);
                    }
                }
            }
        } else {
            const bool xok = (unsigned)gx < (unsigned)IMG;
            #pragma unroll
            for (int j = 0; j < R + 10; ++j) {
                int gy = iy0 + j;
                float a = 0.f, b = 0.f;
                if (xok && (unsigned)gy < (unsigned)IMG) {
                    int off = base + gy * IMG + gx;
                    a = __ldg(img1 + off);
                    b = __ldg(img2 + off);
                }
                float2 ab = make_float2(a, b);
                float2 pq = make_float2(a * a + b * b, a * b);
                #pragma unroll
                for (int o = 0; o < R; ++o) {
                    int k = j - o;
                    if (k >= 0 && k <= 10) {
                        fma2(accAB[o], WPK(k), ab);
                        fma2(accPQ[o], WPK(k), pq);
                    }
                }
            }
        }

        #pragma unroll
        for (int o = 0; o < R; ++o)
            sV[(g * R + o) * SVS + c] =
                make_float4(accAB[o].x, accAB[o].y, accPQ[o].x, accPQ[o].y);
    }
    __syncthreads();

    // ------- Stage H: j-streaming horizontal 11-tap + SSIM, 6 cols/task ----
    float loss = 0.0f;
    for (int t = tid; t < 9 * TILE_Y; t += NT) {     // 9 chunks x 52 rows = 468
        int row = t % TILE_Y;
        int c0  = (t / TILE_Y) * 6;                  // 0..48 (9*6 = 54 exact)

        float2 oAB[6], oPQ[6];
        #pragma unroll
        for (int cc = 0; cc < 6; ++cc) {
            oAB[cc] = make_float2(0.f, 0.f);
            oPQ[cc] = make_float2(0.f, 0.f);
        }

        #pragma unroll
        for (int j = 0; j < 16; ++j) {
            float4 v = sV[row * SVS + c0 + j];
            float2 vab = make_float2(v.x, v.y);
            float2 vpq = make_float2(v.z, v.w);
            #pragma unroll
            for (int cc = 0; cc < 6; ++cc) {
                int k = j - cc;
                if (k >= 0 && k <= 10) {
                    fma2(oAB[cc], WPK(k), vab);
                    fma2(oPQ[cc], WPK(k), vpq);
                }
            }
        }

        int  gy  = y0 + row;
        int  ox0 = x0 + c0;
        bool yok = gy < IMG;

        #pragma unroll
        for (int cc = 0; cc < 6; ++cc) {
            float A = oAB[cc].x, B = oAB[cc].y;
            float P = oPQ[cc].x, Q = oPQ[cc].y;
            float AB   = A * B;
            float AA   = A * A;
            float num1 = 2.0f * AB + C1V;
            float num2 = 2.0f * (Q - AB) + C2V;
            float den1 = fmaf(B, B, C1V) + AA;           // AA+BB+C1
            float den2 = (P - den1) + (C1V + C2V);       // P-AA-BB+C2
            float ssim = __fdividef(num1 * num2, den1 * den2);
            float l    = fmaf(ssim, -0.5f, 0.5f);        // (1-ssim)/2
            l = fminf(fmaxf(l, 0.0f), 0.5f);             // clip (NaN-safe)
            if (yok && (ox0 + cc) < IMG) loss += l;
        }
    }

    // ---------------- Block reduction + last-block finish -------------------
    #pragma unroll
    for (int s = 16; s > 0; s >>= 1)
        loss += __shfl_xor_sync(0xFFFFFFFFu, loss, s);

    __shared__ float warpsum[NT / 32];
    if ((tid & 31) == 0) warpsum[tid >> 5] = loss;
    __syncthreads();
    if (tid == 0) {
        float bsum = 0.f;
        #pragma unroll
        for (int w = 0; w < NT / 32; ++w) bsum += warpsum[w];
        atomicAdd(&g_sum, bsum);
        __threadfence();
        unsigned ticket = atomicAdd(&g_cnt, 1u);
        if (ticket == NBLK - 1) {
            float total = atomicAdd(&g_sum, 0.0f);       // coherent read
            const float inv_total = 1.0f / (16.0f * 3.0f * 512.0f * 512.0f);
            out[0] = total * inv_total;
            g_sum = 0.0f;                                // reset for next replay
            g_cnt = 0u;
        }
    }
}

extern "C" void kernel_launch(void* const* d_in, const int* in_sizes, int n_in,
                              void* d_out, int out_size)
{
    const float* img1 = (const float*)d_in[0];
    const float* img2 = (const float*)d_in[1];
    float* out = (float*)d_out;

    const int smem_bytes = TILE_Y * SVS * (int)sizeof(float4);  // 54080
    cudaFuncSetAttribute(ssim_t52_kernel,
                         cudaFuncAttributeMaxDynamicSharedMemorySize, smem_bytes);

    dim3 grid(GRIDX, GRIDY, 48);   // 10 x 10 x 48 = 4800 blocks
    ssim_t52_kernel<<<grid, NT, smem_bytes>>>(img1, img2, out);
}